// round 16
// baseline (speedup 1.0000x reference)
#include <cuda_runtime.h>
#include <cuda.h>

// R2Ntab: out[b] = (# rules r with h[b,r] > 0.999999) * [w_or>0] + b_or,
// h[b,r] = x_b . rw_r + b_and[r] - relu(rw_r).sum(), rw = w_and masked by
// w_cancel<0 columns. x binary {0,1} => pass <=> 256-bit pattern match
// (x_bits & care_r) == pos_r when all care weights have |w| >= eps
// (= b_and[r]-0.999999); tiny weights -> don't-care or exact fallback.
//
// R16: TMA screen narrowed to 64B/row (features [32g, 32g+16), 16-bit
// signatures, row-pair ballots). Tests whether the ~11 lines/ns sparse
// ceiling has a per-byte component (halved bytes -> ~2x) or is purely
// DRAM-activation-bound (flat). Tile = 256 rows x 64B = 16KB, 512 CTAs.
// Survivors (~1/512 rows) get the exact full 8-word check. Fallback to
// the proven LDG kernel if tensor-map creation is unavailable.

#define FDIM 256
#define RDIM 128
#define TILE_ROWS 256
#define SEG 16                            // floats per screening segment
#define TILE_BYTES (TILE_ROWS * SEG * 4)  // 16384
#define FULLM 0xffffffffu
// fallback kernel config
#define UNROLL 16
#define FB_NTHREADS 256
#define FB_NBLOCKS 740

__device__ unsigned g_pos[8][RDIM];
__device__ unsigned g_care[8][RDIM];
__device__ float    g_thresh[RDIM];
__device__ float    g_rw[RDIM * FDIM];
__device__ int      g_exact_flag[RDIM];

// ---------------------------------------------------------------------------
// PTX helpers
// ---------------------------------------------------------------------------
__device__ __forceinline__ unsigned smem_u32(const void* p) {
    unsigned a;
    asm("{ .reg .u64 t; cvta.to.shared.u64 t, %1; cvt.u32.u64 %0, t; }"
        : "=r"(a) : "l"(p));
    return a;
}
#define MBAR_INIT(addr, cnt) \
    asm volatile("mbarrier.init.shared.b64 [%0], %1;" :: "r"(addr), "r"(cnt) : "memory")
#define MBAR_EXPECT_TX(addr, bytes) \
    asm volatile("mbarrier.arrive.expect_tx.shared.b64 _, [%0], %1;" \
                 :: "r"(addr), "r"(bytes) : "memory")
#define TMA_LOAD_2D(smem, tmapp, c0, c1, mbar) \
    asm volatile("cp.async.bulk.tensor.2d.shared::cta.global.tile.mbarrier::complete_tx::bytes " \
                 "[%0], [%1, {%2, %3}], [%4];" \
                 :: "r"(smem), "l"(tmapp), "r"(c0), "r"(c1), "r"(mbar) : "memory")
__device__ __forceinline__ void mbar_wait(unsigned mbar, unsigned parity) {
    unsigned done;
    asm volatile(
        "{\n\t.reg .pred p;\n\t"
        "mbarrier.try_wait.parity.acquire.cta.shared::cta.b64 p, [%1], %2;\n\t"
        "selp.b32 %0, 1, 0, p;\n\t}"
        : "=r"(done) : "r"(mbar), "r"(parity) : "memory");
    if (!done) {
        asm volatile(
            "{\n\t.reg .pred P1;\n\t"
            "WL_%=:\n\t"
            "mbarrier.try_wait.parity.acquire.cta.shared::cta.b64 P1, [%0], %1, 0x989680;\n\t"
            "@P1 bra.uni WD_%=;\n\t"
            "bra.uni WL_%=;\n\t"
            "WD_%=:\n\t}"
            :: "r"(mbar), "r"(parity) : "memory");
    }
}

// ---------------------------------------------------------------------------
// Prep: one warp per rule. Word w bit j <-> feature 32w + j.
// ---------------------------------------------------------------------------
__global__ void prep_kernel(const float* __restrict__ wc,
                            const float* __restrict__ wa,
                            const float* __restrict__ ba,
                            const float* __restrict__ wo) {
    int gt   = blockIdx.x * blockDim.x + threadIdx.x;
    int r    = gt >> 5;
    int lane = gt & 31;
    if (r >= RDIM) return;

    float eps     = ba[r] - 0.999999f;
    bool  include = wo[r] > 0.0f;

    float relu_sum = 0.f, sum_tiny = 0.f;
    unsigned pos[8], care[8];
#pragma unroll
    for (int w = 0; w < 8; w++) {
        int   f  = 32 * w + lane;
        float wv = (wc[f] < 0.f) ? 0.f : wa[r * FDIM + f];
        g_rw[r * FDIM + f] = wv;
        relu_sum += fmaxf(wv, 0.f);
        float aw   = fabsf(wv);
        bool  must = (aw >= eps);
        if (!must) sum_tiny += aw;
        pos[w]  = __ballot_sync(FULLM, must && (wv > 0.f));
        care[w] = __ballot_sync(FULLM, must && (wv != 0.f));
    }
#pragma unroll
    for (int o = 16; o; o >>= 1) {
        relu_sum += __shfl_xor_sync(FULLM, relu_sum, o);
        sum_tiny += __shfl_xor_sync(FULLM, sum_tiny, o);
    }

    bool afalse = (!include) || (eps <= 0.f);
    bool exact  = (!afalse) && (sum_tiny >= eps);
    if (afalse || exact) {
        // Impossible at EVERY word (and at every 16-bit half): pos has
        // bits outside care, so (x & care) ^ pos != 0 always.
#pragma unroll
        for (int w = 0; w < 8; w++) { pos[w] = 0xFFFFFFFFu; care[w] = 0u; }
    }
    if (lane == 0) {
        g_thresh[r]     = relu_sum - eps;
        g_exact_flag[r] = exact ? 1 : 0;
#pragma unroll
        for (int w = 0; w < 8; w++) { g_pos[w][r] = pos[w]; g_care[w][r] = care[w]; }
    }
}

// ---------------------------------------------------------------------------
// Shared full-row evaluator (rare path): exact 8-word check + fp32 fallback.
// ---------------------------------------------------------------------------
__device__ __forceinline__ void full_row_eval(
    const float* __restrict__ x, float* __restrict__ out,
    int row, int lane, int nx, const int* s_xr, float b0) {
    unsigned xw[8];
#pragma unroll
    for (int w = 0; w < 8; w++) {
        float v = x[(size_t)row * FDIM + 32 * w + lane];
        xw[w] = __ballot_sync(FULLM, v > 0.5f);
    }
    int cnt = 0;
#pragma unroll
    for (int k = 0; k < 4; k++) {
        int r = lane + 32 * k;
        unsigned acc = 0u;
#pragma unroll
        for (int w = 0; w < 8; w++)
            acc |= (xw[w] & g_care[w][r]) ^ g_pos[w][r];
        if (acc == 0u) cnt++;
    }
    for (int e = 0; e < nx; e++) {              // exact fp32 fallback
        int r = s_xr[e];
        float s = 0.f;
#pragma unroll
        for (int w = 0; w < 8; w++) {
            if ((xw[w] >> lane) & 1u)
                s += g_rw[r * FDIM + 32 * w + lane];
        }
#pragma unroll
        for (int o = 16; o; o >>= 1)
            s += __shfl_xor_sync(FULLM, s, o);
        if (lane == 0 && s > g_thresh[r]) cnt++;
    }
#pragma unroll
    for (int o = 16; o; o >>= 1)
        cnt += __shfl_xor_sync(FULLM, cnt, o);
    if (lane == 0) out[row] = (float)cnt + b0;
}

// ---------------------------------------------------------------------------
// TMA main: one CTA per 256-row tile, 64B/row screen, row-pair ballots.
// ---------------------------------------------------------------------------
__global__ void __launch_bounds__(256)
main_tma(const __grid_constant__ CUtensorMap tmap,
         const float* __restrict__ x,
         const float* __restrict__ bor,
         float* __restrict__ out, int B) {
    __shared__ __align__(1024) float s_tile[TILE_ROWS * SEG];
    __shared__ __align__(8) unsigned long long s_mbar;
    __shared__ int s_nx;
    __shared__ int s_xr[RDIM];

    const int tid  = threadIdx.x;
    const int lane = tid & 31;
    const int wid  = tid >> 5;
    const int tile = blockIdx.x;
    const int g    = tile & 7;              // this tile's screening word
    const int row0t = tile * TILE_ROWS;

    if (tid == 0) {
        s_nx = 0;
        MBAR_INIT(smem_u32(&s_mbar), 1);
    }
    __syncthreads();

    if (tid == 0) {                          // issue the gather immediately
        unsigned mb = smem_u32(&s_mbar);
        MBAR_EXPECT_TX(mb, TILE_BYTES);
        TMA_LOAD_2D(smem_u32(s_tile), &tmap, 32 * g, row0t, mb);
    }

    // Overlap with the TMA: exact-flag scan + 16-bit screening masks.
    if (tid < RDIM && g_exact_flag[tid]) {
        int i = atomicAdd(&s_nx, 1);
        s_xr[i] = tid;
    }
    unsigned pg[4], cg[4];
#pragma unroll
    for (int k = 0; k < 4; k++) {
        pg[k] = g_pos[g][lane + 32 * k] & 0xFFFFu;
        cg[k] = g_care[g][lane + 32 * k] & 0xFFFFu;
    }
    __syncthreads();                         // s_nx/s_xr ready
    const int   nx = s_nx;
    const float b0 = bor[0];

    mbar_wait(smem_u32(&s_mbar), 0);

    // Screen: warp wid handles tile rows [wid*32, wid*32+32) as 16 pairs.
    // LDS: lanes 0-15 read row (pair) A's 16 floats, lanes 16-31 row B's.
    const int rbase = wid * 32;
    float v[16];
#pragma unroll
    for (int u = 0; u < 16; u++)
        v[u] = s_tile[(rbase + 2 * u + (lane >> 4)) * SEG + (lane & 15)];

    unsigned candm = 0u;
#pragma unroll
    for (int u = 0; u < 16; u++) {
        unsigned xw = __ballot_sync(FULLM, v[u] > 0.5f);
        unsigned bA = xw & 0xFFFFu;          // row 2u's 16-bit signature
        unsigned bB = xw >> 16;              // row 2u+1's
        bool cA = false, cB = false;
#pragma unroll
        for (int k = 0; k < 4; k++) {
            cA |= (((bA & cg[k]) ^ pg[k]) == 0u);
            cB |= (((bB & cg[k]) ^ pg[k]) == 0u);
        }
        candm |= (((unsigned)cA) << (2 * u)) | (((unsigned)cB) << (2 * u + 1));
    }
    unsigned m = __reduce_or_sync(FULLM, candm);
    if (nx) m = 0xFFFFFFFFu;                 // exact rules: all rows full

    const int grow0 = row0t + rbase;
    {
        int row = grow0 + lane;              // full 32-lane coalesced store
        if (row < B && !((m >> lane) & 1u)) out[row] = b0;
    }
    while (m) {                              // warp-uniform, rare
        int j = __ffs(m) - 1;
        m &= m - 1;
        int row = grow0 + j;
        if (row < B) full_row_eval(x, out, row, lane, nx, s_xr, b0);
    }
}

// ---------------------------------------------------------------------------
// Fallback main (proven LDG path): per-warp word g, 32-bit screen.
// ---------------------------------------------------------------------------
__global__ void __launch_bounds__(FB_NTHREADS, 5)
main_ldg(const float* __restrict__ x,
         const float* __restrict__ bor,
         float* __restrict__ out, int B) {
    __shared__ int s_nx;
    __shared__ int s_xr[RDIM];

    const int tid = threadIdx.x;
    if (tid == 0) s_nx = 0;
    __syncthreads();
    if (tid < RDIM && g_exact_flag[tid]) {
        int i = atomicAdd(&s_nx, 1);
        s_xr[i] = tid;
    }
    __syncthreads();

    const int   lane = tid & 31;
    const int   nx   = s_nx;
    const float b0   = bor[0];

    const int gw = blockIdx.x * (FB_NTHREADS >> 5) + (tid >> 5);
    const int nw = gridDim.x * (FB_NTHREADS >> 5);
    const int g  = gw & 7;

    unsigned pg[4], cg[4];
#pragma unroll
    for (int k = 0; k < 4; k++) {
        pg[k] = g_pos[g][lane + 32 * k];
        cg[k] = g_care[g][lane + 32 * k];
    }

    const int nchunks = B / UNROLL;
    for (int ch = gw; ch < nchunks; ch += nw) {
        int row0 = ch * UNROLL;
        float v[UNROLL];
#pragma unroll
        for (int u = 0; u < UNROLL; u++)
            v[u] = x[(size_t)(row0 + u) * FDIM + 32 * g + lane];
        unsigned candm = 0u;
#pragma unroll
        for (int u = 0; u < UNROLL; u++) {
            unsigned xw = __ballot_sync(FULLM, v[u] > 0.5f);
            bool cand = false;
#pragma unroll
            for (int k = 0; k < 4; k++)
                cand |= (((xw & cg[k]) ^ pg[k]) == 0u);
            candm |= ((unsigned)cand) << u;
        }
        unsigned m = __reduce_or_sync(FULLM, candm);
        if (nx) m = (1u << UNROLL) - 1u;
        if (lane < UNROLL && !((m >> lane) & 1u))
            out[row0 + lane] = b0;
        while (m) {
            int j = __ffs(m) - 1;
            m &= m - 1;
            full_row_eval(x, out, row0 + j, lane, nx, s_xr, b0);
        }
    }
    for (int row = nchunks * UNROLL + gw; row < B; row += nw)
        full_row_eval(x, out, row, lane, nx, s_xr, b0);
}

// ---------------------------------------------------------------------------
// Host
// ---------------------------------------------------------------------------
typedef CUresult (*EncodeTiledFn)(
    CUtensorMap*, CUtensorMapDataType, cuuint32_t, void*,
    const cuuint64_t*, const cuuint64_t*, const cuuint32_t*, const cuuint32_t*,
    CUtensorMapInterleave, CUtensorMapSwizzle, CUtensorMapL2promotion,
    CUtensorMapFloatOOBfill);

extern "C" void kernel_launch(void* const* d_in, const int* in_sizes, int n_in,
                              void* d_out, int out_size) {
    const float* x  = (const float*)d_in[0];   // [B, 256] binary
    const float* wc = (const float*)d_in[1];   // [256]
    const float* wa = (const float*)d_in[2];   // [128, 256]
    const float* ba = (const float*)d_in[3];   // [128]
    const float* wo = (const float*)d_in[4];   // [1, 128]
    const float* bo = (const float*)d_in[5];   // [1]
    float* out = (float*)d_out;

    int B = in_sizes[0] / FDIM;

    prep_kernel<<<16, 256>>>(wc, wa, ba, wo);  // 128 warps, 1 per rule

    // Resolve cuTensorMapEncodeTiled through the runtime (no -lcuda dep).
    void* fp = nullptr;
    cudaDriverEntryPointQueryResult qr = cudaDriverEntryPointSymbolNotFound;
    cudaGetDriverEntryPointByVersion("cuTensorMapEncodeTiled", &fp, 12000,
                                     cudaEnableDefault, &qr);
    bool tma_ok = (qr == cudaDriverEntryPointSuccess) && fp;

    CUtensorMap tmap;
    if (tma_ok) {
        cuuint64_t dims[2]    = {(cuuint64_t)FDIM, (cuuint64_t)B};
        cuuint64_t strides[1] = {(cuuint64_t)FDIM * 4};
        cuuint32_t box[2]     = {SEG, TILE_ROWS};
        cuuint32_t estr[2]    = {1, 1};
        CUresult r = ((EncodeTiledFn)fp)(
            &tmap, CU_TENSOR_MAP_DATA_TYPE_FLOAT32, 2, (void*)x,
            dims, strides, box, estr,
            CU_TENSOR_MAP_INTERLEAVE_NONE, CU_TENSOR_MAP_SWIZZLE_NONE,
            CU_TENSOR_MAP_L2_PROMOTION_L2_128B,
            CU_TENSOR_MAP_FLOAT_OOB_FILL_NONE);
        tma_ok = (r == CUDA_SUCCESS);
    }

    if (tma_ok) {
        int ntiles = (B + TILE_ROWS - 1) / TILE_ROWS;
        main_tma<<<ntiles, 256>>>(tmap, x, bo, out, B);
    } else {
        main_ldg<<<FB_NBLOCKS, FB_NTHREADS>>>(x, bo, out, B);
    }
}

// round 17
// speedup vs baseline: 3.7175x; 3.7175x over previous
#include <cuda_runtime.h>
#include <cuda.h>

// R2Ntab: out[b] = (# rules r with h[b,r] > 0.999999) * [w_or>0] + b_or,
// h[b,r] = x_b . rw_r + b_and[r] - relu(rw_r).sum(), rw = w_and masked by
// w_cancel<0 columns. x binary {0,1} => pass <=> 256-bit pattern match
// (x_bits & care_r) == pos_r when all care weights have |w| >= eps
// (= b_and[r]-0.999999); tiny weights -> don't-care or exact fallback.
//
// R17 = R15 (best: TMA 128B-per-row screen, box {32,128}, per-tile word
// g = tile&7) + PDL overlap: main_tma launches with programmatic stream
// serialization, issues its TMA gather immediately (depends only on x),
// and cudaGridDependencySynchronize()s before reading prep's mask tables.
// Prep cost + launch gap hide under the TMA flight. The sparse screen is
// DRAM-line/activation-bound (~10.5 lines/ns across LDG/TMA variants), so
// the main kernel is at its floor; this round removes serialization.

#define FDIM 256
#define RDIM 128
#define TILE_ROWS 128
#define SEG 32                          // floats per screening segment
#define TILE_BYTES (TILE_ROWS * SEG * 4)   // 16384
#define FULLM 0xffffffffu
// fallback kernel config
#define UNROLL 16
#define FB_NTHREADS 256
#define FB_NBLOCKS 740

__device__ unsigned g_pos[8][RDIM];
__device__ unsigned g_care[8][RDIM];
__device__ float    g_thresh[RDIM];
__device__ float    g_rw[RDIM * FDIM];
__device__ int      g_exact_flag[RDIM];

// ---------------------------------------------------------------------------
// PTX helpers
// ---------------------------------------------------------------------------
__device__ __forceinline__ unsigned smem_u32(const void* p) {
    unsigned a;
    asm("{ .reg .u64 t; cvta.to.shared.u64 t, %1; cvt.u32.u64 %0, t; }"
        : "=r"(a) : "l"(p));
    return a;
}
#define MBAR_INIT(addr, cnt) \
    asm volatile("mbarrier.init.shared.b64 [%0], %1;" :: "r"(addr), "r"(cnt) : "memory")
#define MBAR_EXPECT_TX(addr, bytes) \
    asm volatile("mbarrier.arrive.expect_tx.shared.b64 _, [%0], %1;" \
                 :: "r"(addr), "r"(bytes) : "memory")
#define TMA_LOAD_2D(smem, tmapp, c0, c1, mbar) \
    asm volatile("cp.async.bulk.tensor.2d.shared::cta.global.tile.mbarrier::complete_tx::bytes " \
                 "[%0], [%1, {%2, %3}], [%4];" \
                 :: "r"(smem), "l"(tmapp), "r"(c0), "r"(c1), "r"(mbar) : "memory")
__device__ __forceinline__ void mbar_wait(unsigned mbar, unsigned parity) {
    unsigned done;
    asm volatile(
        "{\n\t.reg .pred p;\n\t"
        "mbarrier.try_wait.parity.acquire.cta.shared::cta.b64 p, [%1], %2;\n\t"
        "selp.b32 %0, 1, 0, p;\n\t}"
        : "=r"(done) : "r"(mbar), "r"(parity) : "memory");
    if (!done) {
        asm volatile(
            "{\n\t.reg .pred P1;\n\t"
            "WL_%=:\n\t"
            "mbarrier.try_wait.parity.acquire.cta.shared::cta.b64 P1, [%0], %1, 0x989680;\n\t"
            "@P1 bra.uni WD_%=;\n\t"
            "bra.uni WL_%=;\n\t"
            "WD_%=:\n\t}"
            :: "r"(mbar), "r"(parity) : "memory");
    }
}

// ---------------------------------------------------------------------------
// Prep: one warp per rule. Word w bit j <-> feature 32w + j.
// ---------------------------------------------------------------------------
__global__ void prep_kernel(const float* __restrict__ wc,
                            const float* __restrict__ wa,
                            const float* __restrict__ ba,
                            const float* __restrict__ wo) {
    // Allow the PDL-serialized main kernel to begin launching now; its
    // cudaGridDependencySynchronize() still waits for OUR full completion
    // before it reads any g_* table.
    cudaTriggerProgrammaticLaunchCompletion();

    int gt   = blockIdx.x * blockDim.x + threadIdx.x;
    int r    = gt >> 5;
    int lane = gt & 31;
    if (r >= RDIM) return;

    float eps     = ba[r] - 0.999999f;
    bool  include = wo[r] > 0.0f;

    float relu_sum = 0.f, sum_tiny = 0.f;
    unsigned pos[8], care[8];
#pragma unroll
    for (int w = 0; w < 8; w++) {
        int   f  = 32 * w + lane;
        float wv = (wc[f] < 0.f) ? 0.f : wa[r * FDIM + f];
        g_rw[r * FDIM + f] = wv;
        relu_sum += fmaxf(wv, 0.f);
        float aw   = fabsf(wv);
        bool  must = (aw >= eps);
        if (!must) sum_tiny += aw;
        pos[w]  = __ballot_sync(FULLM, must && (wv > 0.f));
        care[w] = __ballot_sync(FULLM, must && (wv != 0.f));
    }
#pragma unroll
    for (int o = 16; o; o >>= 1) {
        relu_sum += __shfl_xor_sync(FULLM, relu_sum, o);
        sum_tiny += __shfl_xor_sync(FULLM, sum_tiny, o);
    }

    bool afalse = (!include) || (eps <= 0.f);
    bool exact  = (!afalse) && (sum_tiny >= eps);
    if (afalse || exact) {
        // Impossible at EVERY word: pos has bits outside care, so
        // (x & care) ^ pos != 0 always -> any screen rejects them.
#pragma unroll
        for (int w = 0; w < 8; w++) { pos[w] = 0xFFFFFFFFu; care[w] = 0u; }
    }
    if (lane == 0) {
        g_thresh[r]     = relu_sum - eps;
        g_exact_flag[r] = exact ? 1 : 0;
#pragma unroll
        for (int w = 0; w < 8; w++) { g_pos[w][r] = pos[w]; g_care[w][r] = care[w]; }
    }
}

// ---------------------------------------------------------------------------
// Shared full-row evaluator (rare path): exact 8-word check + fp32 fallback.
// ---------------------------------------------------------------------------
__device__ __forceinline__ void full_row_eval(
    const float* __restrict__ x, float* __restrict__ out,
    int row, int lane, int nx, const int* s_xr, float b0) {
    unsigned xw[8];
#pragma unroll
    for (int w = 0; w < 8; w++) {
        float v = x[(size_t)row * FDIM + 32 * w + lane];
        xw[w] = __ballot_sync(FULLM, v > 0.5f);
    }
    int cnt = 0;
#pragma unroll
    for (int k = 0; k < 4; k++) {
        int r = lane + 32 * k;
        unsigned acc = 0u;
#pragma unroll
        for (int w = 0; w < 8; w++)
            acc |= (xw[w] & g_care[w][r]) ^ g_pos[w][r];
        if (acc == 0u) cnt++;
    }
    for (int e = 0; e < nx; e++) {              // exact fp32 fallback
        int r = s_xr[e];
        float s = 0.f;
#pragma unroll
        for (int w = 0; w < 8; w++) {
            if ((xw[w] >> lane) & 1u)
                s += g_rw[r * FDIM + 32 * w + lane];
        }
#pragma unroll
        for (int o = 16; o; o >>= 1)
            s += __shfl_xor_sync(FULLM, s, o);
        if (lane == 0 && s > g_thresh[r]) cnt++;
    }
#pragma unroll
    for (int o = 16; o; o >>= 1)
        cnt += __shfl_xor_sync(FULLM, cnt, o);
    if (lane == 0) out[row] = (float)cnt + b0;
}

// ---------------------------------------------------------------------------
// TMA main: one CTA per 128-row tile. UTMALDG gathers 128 x 128B word-g
// segments into SMEM; 8 warps screen 16 rows each from SMEM. PDL: the TMA
// issue depends only on x; prep results are read after the grid-dependency
// sync, hiding prep + launch latency under the TMA flight.
// ---------------------------------------------------------------------------
__global__ void __launch_bounds__(256)
main_tma(const __grid_constant__ CUtensorMap tmap,
         const float* __restrict__ x,
         const float* __restrict__ bor,
         float* __restrict__ out, int B) {
    __shared__ __align__(1024) float s_tile[TILE_ROWS * SEG];
    __shared__ __align__(8) unsigned long long s_mbar;
    __shared__ int s_nx;
    __shared__ int s_xr[RDIM];

    const int tid  = threadIdx.x;
    const int lane = tid & 31;
    const int wid  = tid >> 5;
    const int tile = blockIdx.x;
    const int g    = tile & 7;              // this tile's screening word
    const int row0t = tile * TILE_ROWS;

    if (tid == 0) {
        s_nx = 0;
        MBAR_INIT(smem_u32(&s_mbar), 1);
    }
    __syncthreads();

    if (tid == 0) {                          // fire the gather immediately
        unsigned mb = smem_u32(&s_mbar);
        MBAR_EXPECT_TX(mb, TILE_BYTES);
        TMA_LOAD_2D(smem_u32(s_tile), &tmap, SEG * g, row0t, mb);
    }

    // Wait for prep to finish before touching its outputs (no-op when
    // launched without PDL). The TMA above is already in flight.
    cudaGridDependencySynchronize();

    if (tid < RDIM && g_exact_flag[tid]) {
        int i = atomicAdd(&s_nx, 1);
        s_xr[i] = tid;
    }
    unsigned pg[4], cg[4];
#pragma unroll
    for (int k = 0; k < 4; k++) {
        pg[k] = g_pos[g][lane + 32 * k];
        cg[k] = g_care[g][lane + 32 * k];
    }
    __syncthreads();                         // s_nx/s_xr ready
    const int   nx = s_nx;
    const float b0 = bor[0];

    mbar_wait(smem_u32(&s_mbar), 0);

    // Screen: warp wid handles tile rows [wid*16, wid*16+16).
    const int rbase = wid * 16;
    float v[16];
#pragma unroll
    for (int u = 0; u < 16; u++)
        v[u] = s_tile[(rbase + u) * SEG + lane];

    unsigned candm = 0u;
#pragma unroll
    for (int u = 0; u < 16; u++) {
        unsigned xw = __ballot_sync(FULLM, v[u] > 0.5f);
        bool cand = false;
#pragma unroll
        for (int k = 0; k < 4; k++)
            cand |= (((xw & cg[k]) ^ pg[k]) == 0u);
        candm |= ((unsigned)cand) << u;
    }
    unsigned m = __reduce_or_sync(FULLM, candm);
    if (nx) m = 0xFFFFu;                     // exact rules: all rows full

    const int grow0 = row0t + rbase;
    if (lane < 16) {
        int row = grow0 + lane;
        if (row < B && !((m >> lane) & 1u)) out[row] = b0;
    }
    while (m) {                              // warp-uniform, rare
        int j = __ffs(m) - 1;
        m &= m - 1;
        int row = grow0 + j;
        if (row < B) full_row_eval(x, out, row, lane, nx, s_xr, b0);
    }
}

// ---------------------------------------------------------------------------
// Fallback main (proven LDG path): per-warp word g, 32-bit screen.
// ---------------------------------------------------------------------------
__global__ void __launch_bounds__(FB_NTHREADS, 5)
main_ldg(const float* __restrict__ x,
         const float* __restrict__ bor,
         float* __restrict__ out, int B) {
    __shared__ int s_nx;
    __shared__ int s_xr[RDIM];

    const int tid = threadIdx.x;
    if (tid == 0) s_nx = 0;
    __syncthreads();
    if (tid < RDIM && g_exact_flag[tid]) {
        int i = atomicAdd(&s_nx, 1);
        s_xr[i] = tid;
    }
    __syncthreads();

    const int   lane = tid & 31;
    const int   nx   = s_nx;
    const float b0   = bor[0];

    const int gw = blockIdx.x * (FB_NTHREADS >> 5) + (tid >> 5);
    const int nw = gridDim.x * (FB_NTHREADS >> 5);
    const int g  = gw & 7;

    unsigned pg[4], cg[4];
#pragma unroll
    for (int k = 0; k < 4; k++) {
        pg[k] = g_pos[g][lane + 32 * k];
        cg[k] = g_care[g][lane + 32 * k];
    }

    const int nchunks = B / UNROLL;
    for (int ch = gw; ch < nchunks; ch += nw) {
        int row0 = ch * UNROLL;
        float v[UNROLL];
#pragma unroll
        for (int u = 0; u < UNROLL; u++)
            v[u] = x[(size_t)(row0 + u) * FDIM + 32 * g + lane];
        unsigned candm = 0u;
#pragma unroll
        for (int u = 0; u < UNROLL; u++) {
            unsigned xw = __ballot_sync(FULLM, v[u] > 0.5f);
            bool cand = false;
#pragma unroll
            for (int k = 0; k < 4; k++)
                cand |= (((xw & cg[k]) ^ pg[k]) == 0u);
            candm |= ((unsigned)cand) << u;
        }
        unsigned m = __reduce_or_sync(FULLM, candm);
        if (nx) m = (1u << UNROLL) - 1u;
        if (lane < UNROLL && !((m >> lane) & 1u))
            out[row0 + lane] = b0;
        while (m) {
            int j = __ffs(m) - 1;
            m &= m - 1;
            full_row_eval(x, out, row0 + j, lane, nx, s_xr, b0);
        }
    }
    for (int row = nchunks * UNROLL + gw; row < B; row += nw)
        full_row_eval(x, out, row, lane, nx, s_xr, b0);
}

// ---------------------------------------------------------------------------
// Host
// ---------------------------------------------------------------------------
typedef CUresult (*EncodeTiledFn)(
    CUtensorMap*, CUtensorMapDataType, cuuint32_t, void*,
    const cuuint64_t*, const cuuint64_t*, const cuuint32_t*, const cuuint32_t*,
    CUtensorMapInterleave, CUtensorMapSwizzle, CUtensorMapL2promotion,
    CUtensorMapFloatOOBfill);

extern "C" void kernel_launch(void* const* d_in, const int* in_sizes, int n_in,
                              void* d_out, int out_size) {
    const float* x  = (const float*)d_in[0];   // [B, 256] binary
    const float* wc = (const float*)d_in[1];   // [256]
    const float* wa = (const float*)d_in[2];   // [128, 256]
    const float* ba = (const float*)d_in[3];   // [128]
    const float* wo = (const float*)d_in[4];   // [1, 128]
    const float* bo = (const float*)d_in[5];   // [1]
    float* out = (float*)d_out;

    int B = in_sizes[0] / FDIM;

    prep_kernel<<<16, 256>>>(wc, wa, ba, wo);  // 128 warps, 1 per rule

    // Resolve cuTensorMapEncodeTiled through the runtime (no -lcuda dep).
    void* fp = nullptr;
    cudaDriverEntryPointQueryResult qr = cudaDriverEntryPointSymbolNotFound;
    cudaGetDriverEntryPointByVersion("cuTensorMapEncodeTiled", &fp, 12000,
                                     cudaEnableDefault, &qr);
    bool tma_ok = (qr == cudaDriverEntryPointSuccess) && fp;

    CUtensorMap tmap;
    if (tma_ok) {
        cuuint64_t dims[2]    = {(cuuint64_t)FDIM, (cuuint64_t)B};
        cuuint64_t strides[1] = {(cuuint64_t)FDIM * 4};
        cuuint32_t box[2]     = {SEG, TILE_ROWS};
        cuuint32_t estr[2]    = {1, 1};
        CUresult r = ((EncodeTiledFn)fp)(
            &tmap, CU_TENSOR_MAP_DATA_TYPE_FLOAT32, 2, (void*)x,
            dims, strides, box, estr,
            CU_TENSOR_MAP_INTERLEAVE_NONE, CU_TENSOR_MAP_SWIZZLE_NONE,
            CU_TENSOR_MAP_L2_PROMOTION_L2_128B,
            CU_TENSOR_MAP_FLOAT_OOB_FILL_NONE);
        tma_ok = (r == CUDA_SUCCESS);
    }

    if (tma_ok) {
        int ntiles = (B + TILE_ROWS - 1) / TILE_ROWS;

        // PDL: overlap main's launch + TMA prologue with prep's tail.
        cudaLaunchConfig_t cfg = {};
        cfg.gridDim  = {(unsigned)ntiles, 1, 1};
        cfg.blockDim = {256, 1, 1};
        cudaLaunchAttribute attrs[1];
        attrs[0].id = cudaLaunchAttributeProgrammaticStreamSerialization;
        attrs[0].val.programmaticStreamSerializationAllowed = 1;
        cfg.attrs = attrs;
        cfg.numAttrs = 1;

        cudaError_t lr = cudaLaunchKernelEx(&cfg, main_tma,
                                            tmap, x, bo, out, B);
        if (lr != cudaSuccess)               // PDL unsupported: plain launch
            main_tma<<<ntiles, 256>>>(tmap, x, bo, out, B);
    } else {
        main_ldg<<<FB_NBLOCKS, FB_NTHREADS>>>(x, bo, out, B);
    }
}